// round 16
// baseline (speedup 1.0000x reference)
#include <cuda_runtime.h>
#include <cfloat>
#include <cstdint>

// Shapes (fixed by the problem)
#define BQ 8
#define NQ 16384
#define DQ 768
#define CQ 8
#define NCQ 2

#define THREADS 256
#define NWARP 8
#define NSLOT 4                                   // per-warp ring depth
#define ROW_BYTES (DQ * 4)                        // 3072
#define ROW_F4 (DQ / 4)                           // 192
#define WARP_RING_BYTES (NSLOT * ROW_BYTES)       // 12288
#define SMEM_DATA (NWARP * WARP_RING_BYTES)       // 98304 (96KB)

#define GRID 304                                  // 2 blocks x 152 SMs, one wave
#define TOTAL_ROWS (BQ * NQ)                      // 131072
#define QR (TOTAL_ROWS / GRID)                    // 431
#define RR (TOTAL_ROWS - QR * GRID)               // 48

// Scratch per (batch, cluster): [dot_w0_sum, dot_w1_sum, count].
// Zero at module load; the finalizing block re-zeros it each replay.
__device__ float        g_accum[BQ * CQ * 3];
__device__ unsigned int g_ticket;

// ---- mbarrier / bulk-copy PTX helpers ----
__device__ __forceinline__ unsigned smem_u32(const void* p) {
    return (unsigned)__cvta_generic_to_shared(p);
}
__device__ __forceinline__ void mbar_init(unsigned a, unsigned cnt) {
    asm volatile("mbarrier.init.shared::cta.b64 [%0], %1;" :: "r"(a), "r"(cnt) : "memory");
}
__device__ __forceinline__ void mbar_expect_tx(unsigned a, unsigned bytes) {
    asm volatile("mbarrier.arrive.expect_tx.shared::cta.b64 _, [%0], %1;"
                 :: "r"(a), "r"(bytes) : "memory");
}
__device__ __forceinline__ void mbar_wait(unsigned a, unsigned parity) {
    asm volatile(
        "{\n\t.reg .pred P;\n"
        "W%=:\n\tmbarrier.try_wait.parity.shared::cta.b64 P, [%0], %1, 0x989680;\n"
        "\t@P bra D%=;\n\tbra W%=;\nD%=:\n\t}"
        :: "r"(a), "r"(parity) : "memory");
}
__device__ __forceinline__ void bulk_g2s(unsigned dst, const void* src,
                                         unsigned bytes, unsigned bar) {
    asm volatile(
        "cp.async.bulk.shared::cta.global.mbarrier::complete_tx::bytes "
        "[%0], [%1], %2, [%3];"
        :: "r"(dst), "l"(src), "r"(bytes), "r"(bar) : "memory");
}
__device__ __forceinline__ void fence_proxy_async_cta() {
    asm volatile("fence.proxy.async.shared::cta;" ::: "memory");
}

__global__ __launch_bounds__(THREADS, 2) void fused_kernel(
    const float* __restrict__ x,      // [B, N, D]
    const int*   __restrict__ labels, // [B, N]
    const float* __restrict__ w,      // [NC, D]
    const float* __restrict__ hb,     // [NC]
    float*       __restrict__ out)    // [B, NC]
{
    extern __shared__ float4 s_x[];          // 8 warps x 4 slots x 3KB
    __shared__ float s_bins[BQ * CQ * 3];
    __shared__ int   s_last;
    __shared__ __align__(8) unsigned long long s_full[NWARP][NSLOT];

    const int tid  = threadIdx.x;
    const int lane = tid & 31;
    const int warp = tid >> 5;
    const int bid  = blockIdx.x;

    if (tid < BQ * CQ * 3) s_bins[tid] = 0.0f;
    if (lane < NSLOT) mbar_init(smem_u32(&s_full[warp][lane]), 1);
    __syncthreads();

    unsigned full_b[NSLOT];
    #pragma unroll
    for (int s = 0; s < NSLOT; s++) full_b[s] = smem_u32(&s_full[warp][s]);
    const unsigned ring_base = smem_u32(s_x) + warp * WARP_RING_BYTES;
    const float4*  ring_f4   = s_x + warp * (WARP_RING_BYTES / 16);

    // head_w in registers: lane l owns float4 chunks {l + 32k}, k = 0..5.
    float4 w0[6], w1[6];
    {
        const float4* w0v = reinterpret_cast<const float4*>(w);
        const float4* w1v = reinterpret_cast<const float4*>(w + DQ);
        #pragma unroll
        for (int k = 0; k < 6; k++) {
            w0[k] = w0v[lane + 32 * k];
            w1[k] = w1v[lane + 32 * k];
        }
    }

    // Block's contiguous row range; warps interleave stride-8 inside it.
    const int n_rows = QR + (bid < RR ? 1 : 0);
    const int start  = bid * QR + (bid < RR ? bid : RR);
    const int n_it   = (n_rows - warp + NWARP - 1) / NWARP;   // rows for this warp

    // Per-thread per-cluster accumulators; lane i (i<8) counts cluster-i rows.
    float acc0[CQ], acc1[CQ];
    #pragma unroll
    for (int i = 0; i < CQ; i++) { acc0[i] = 0.0f; acc1[i] = 0.0f; }
    int my_cnt = 0;
    int cur_b  = (start + warp) / NQ;

    // Prologue: lane 0 fills this warp's ring.
    if (lane == 0) {
        #pragma unroll
        for (int j = 0; j < NSLOT; j++) {
            if (j < n_it) {
                mbar_expect_tx(full_b[j], ROW_BYTES);
                bulk_g2s(ring_base + j * ROW_BYTES,
                         x + (size_t)(start + warp + j * NWARP) * DQ,
                         ROW_BYTES, full_b[j]);
            }
        }
    }

    #define FLUSH_WARP(bb)                                                       \
        do {                                                                     \
            _Pragma("unroll")                                                    \
            for (int _i = 0; _i < CQ; _i++) {                                    \
                _Pragma("unroll")                                                \
                for (int _o = 16; _o > 0; _o >>= 1) {                            \
                    acc0[_i] += __shfl_down_sync(0xffffffffu, acc0[_i], _o);     \
                    acc1[_i] += __shfl_down_sync(0xffffffffu, acc1[_i], _o);     \
                }                                                                \
            }                                                                    \
            if (lane == 0) {                                                     \
                _Pragma("unroll")                                                \
                for (int _i = 0; _i < CQ; _i++) {                                \
                    atomicAdd(&s_bins[((bb) * CQ + _i) * 3 + 0], acc0[_i]);      \
                    atomicAdd(&s_bins[((bb) * CQ + _i) * 3 + 1], acc1[_i]);      \
                }                                                                \
            }                                                                    \
            if (lane < CQ && my_cnt > 0)                                         \
                atomicAdd(&s_bins[((bb) * CQ + lane) * 3 + 2], (float)my_cnt);   \
            _Pragma("unroll")                                                    \
            for (int _i = 0; _i < CQ; _i++) { acc0[_i] = 0.0f; acc1[_i] = 0.0f; }\
            my_cnt = 0;                                                          \
        } while (0)

    for (int it = 0; it < n_it; it++) {
        const int slot = it & (NSLOT - 1);
        const int row  = start + warp + it * NWARP;
        const int b    = row / NQ;                 // warp-uniform
        if (b != cur_b) { FLUSH_WARP(cur_b); cur_b = b; }

        const int c = __ldg(&labels[row]);         // warp-uniform broadcast

        mbar_wait(full_b[slot], (unsigned)((it >> 2) & 1));

        const float4* rp = ring_f4 + slot * ROW_F4;
        float d0 = 0.0f, d1 = 0.0f;
        #pragma unroll
        for (int k = 0; k < 6; k++) {
            const float4 vv = rp[lane + 32 * k];   // conflict-free LDS.128
            d0 = fmaf(vv.x, w0[k].x, d0); d0 = fmaf(vv.y, w0[k].y, d0);
            d0 = fmaf(vv.z, w0[k].z, d0); d0 = fmaf(vv.w, w0[k].w, d0);
            d1 = fmaf(vv.x, w1[k].x, d1); d1 = fmaf(vv.y, w1[k].y, d1);
            d1 = fmaf(vv.z, w1[k].z, d1); d1 = fmaf(vv.w, w1[k].w, d1);
        }
        #pragma unroll
        for (int i = 0; i < CQ; i++) {
            if (c == i) { acc0[i] += d0; acc1[i] += d1; }
        }
        if (lane == c) my_cnt++;

        // Immediate per-warp refill of the just-freed slot (no empty barrier:
        // this warp is the sole consumer; lockstep issue means every lane's
        // LDS results were consumed before this point).
        __syncwarp();
        if (lane == 0 && it + NSLOT < n_it) {
            fence_proxy_async_cta();               // order LDS reads vs TMA write
            mbar_expect_tx(full_b[slot], ROW_BYTES);
            bulk_g2s(ring_base + slot * ROW_BYTES,
                     x + (size_t)(row + NSLOT * NWARP) * DQ,
                     ROW_BYTES, full_b[slot]);
        }
    }
    FLUSH_WARP(cur_b);
    #undef FLUSH_WARP

    __syncthreads();
    if (tid < BQ * CQ * 3) atomicAdd(&g_accum[tid], s_bins[tid]);
    __threadfence();   // order this block's global atomics before the ticket
    __syncthreads();

    if (tid == 0) {
        unsigned t = atomicAdd(&g_ticket, 1u);
        s_last = (t == (unsigned)(GRID - 1)) ? 1 : 0;
    }
    __syncthreads();
    if (!s_last) return;

    // ---- last block: finalize ----
    __threadfence();
    float bl0 = 0.0f, bl1 = 0.0f;
    const bool isb = (tid < BQ);
    if (isb) {
        const float b0 = hb[0], b1 = hb[1];
        float best = -FLT_MAX;
        #pragma unroll
        for (int c = 0; c < CQ; c++) {
            const float s0 = __ldcg(&g_accum[(tid * CQ + c) * 3 + 0]);
            const float s1 = __ldcg(&g_accum[(tid * CQ + c) * 3 + 1]);
            const float cn = __ldcg(&g_accum[(tid * CQ + c) * 3 + 2]);
            const float inv = 1.0f / fmaxf(cn, 1.0f);
            const float l0 = s0 * inv + b0;
            const float l1 = s1 * inv + b1;
            // NC=2: 1 - softmax(l)[0] = sigmoid(l1 - l0), monotone in (l1 - l0).
            const float score = l1 - l0;
            if (score > best) { best = score; bl0 = l0; bl1 = l1; }
        }
    }
    __syncthreads();   // all reads of g_accum done before reset
    if (tid < BQ * CQ * 3) g_accum[tid] = 0.0f;   // self-reset for next replay
    if (tid == 0) g_ticket = 0u;
    if (isb) {
        out[tid * NCQ + 0] = bl0;
        out[tid * NCQ + 1] = bl1;
    }
}

extern "C" void kernel_launch(void* const* d_in, const int* in_sizes, int n_in,
                              void* d_out, int out_size)
{
    const float* x      = (const float*)d_in[0]; // inst_feat [8,16384,768] f32
    const int*   labels = (const int*)  d_in[1]; // [8,16384] i32
    const float* w      = (const float*)d_in[2]; // head_w [2,768] f32
    const float* hb     = (const float*)d_in[3]; // head_b [2] f32
    float* out = (float*)d_out;                  // [8,2] f32

    cudaFuncSetAttribute(fused_kernel,
                         cudaFuncAttributeMaxDynamicSharedMemorySize, SMEM_DATA);
    fused_kernel<<<GRID, THREADS, SMEM_DATA>>>(x, labels, w, hb, out);
}